// round 16
// baseline (speedup 1.0000x reference)
#include <cuda_runtime.h>
#include <cuda_bf16.h>
#include <math.h>
#include <stdint.h>

#define NROWS    65536
#define DIMK     64
#define CB       1024
#define TOPKK    3
#define THREADS  256
#define NBLOCKS  512
#define RPB      128
#define CHUNK    128
#define NCHUNK   8
#define BSTRIDE  72       // bf16 per code row in smem: bank-spread stride

// Output layout (concatenated reference tuple, fp32):
//   z_q_st [4194304] | loss [1] | perplexity [1] | encodings [201326592] | idx [196608]
#define OFF_LOSS 4194304ull
#define OFF_PERP 4194305ull
#define OFF_ENC  4194306ull   // float index % 4 == 2 -> 8B-aligned base
#define OFF_IDX  205520898ull

__device__ unsigned int g_hist[CB];
__device__ float        g_blk_loss[NBLOCKS];
__device__ unsigned int g_done;

static __device__ __forceinline__ uint32_t bf2(float lo, float hi) {
    uint32_t r;
    asm("cvt.rn.bf16x2.f32 %0, %1, %2;" : "=r"(r) : "f"(hi), "f"(lo));
    return r;
}

// branchless insert of key v into ascending sorted 4-array (IMNMX chain)
static __device__ __forceinline__ void insk(int v, int* ck) {
    #pragma unroll
    for (int s = 0; s < 4; s++) {
        int mn = min(ck[s], v);
        int mx = max(ck[s], v);
        ck[s] = mn; v = mx;
    }
}
// insert (d, gi) into sorted triple, lexicographic (tie -> lower idx)
static __device__ __forceinline__ void ins3(float d, int gi,
                                            float& s0, float& s1, float& s2,
                                            int& i0, int& i1, int& i2) {
    if (d < s2 || (d == s2 && gi < i2)) {
        if (d < s1 || (d == s1 && gi < i1)) {
            s2 = s1; i2 = i1;
            if (d < s0 || (d == s0 && gi < i0)) { s1 = s0; i1 = i0; s0 = d; i0 = gi; }
            else                                { s1 = d;  i1 = gi; }
        } else { s2 = d; i2 = gi; }
    }
}

__global__ void __launch_bounds__(THREADS, 3) vq_mma(
    const float* __restrict__ z, const float* __restrict__ emb, float* __restrict__ out)
{
    __shared__ __align__(16) uint16_t Bs[CHUNK * BSTRIDE];   // bf16 codebook chunk
    __shared__ float esq_s[CB];     // |e|^2 exact (rescore)
    __shared__ float esq22_s[CB];   // |e|^2 * 2^22 (key path)
    __shared__ float zsq_s[RPB];
    __shared__ int   tidx[RPB * 3];
    __shared__ float red[16];
    __shared__ int   lastf;

    const int t    = threadIdx.x;
    const int b    = blockIdx.x;
    const int lane = t & 31;
    const int w    = t >> 5;          // warp 0..7: owns rows w*16 .. w*16+15
    const int g    = lane >> 2;       // group 0..7 (row-in-tile / B column)
    const int q    = lane & 3;        // quad 0..3  (k-pair / D column pair)

    // ---- |z|^2 for rows (first 128 threads) ----
    if (t < RPB) {
        const float4* zr = (const float4*)(z + (size_t)(b * RPB + t) * DIMK);
        float s = 0.f;
        #pragma unroll
        for (int i = 0; i < 16; i++) {
            float4 v = __ldg(zr + i);
            s += v.x*v.x; s += v.y*v.y; s += v.z*v.z; s += v.w*v.w;
        }
        zsq_s[t] = s;
    }
    // ---- |e|^2 for all 1024 codes (exact + scaled key base) ----
    #pragma unroll
    for (int p = 0; p < 4; p++) {
        const int code = p * THREADS + t;
        const float4* er = (const float4*)(emb + (size_t)code * DIMK);
        float s = 0.f;
        #pragma unroll
        for (int i = 0; i < 16; i++) {
            float4 v = __ldg(er + i);
            s += v.x*v.x; s += v.y*v.y; s += v.z*v.z; s += v.w*v.w;
        }
        esq_s[code]   = s;
        esq22_s[code] = s * 4194304.0f;   // 2^22
    }
    __syncthreads();

    // ---- A fragments: this warp's 16 z rows as bf16, register-resident ----
    // m16n8k16 A map: a0=[g][2q,2q+1] a1=[g+8][..] a2=[g][2q+8..] a3=[g+8][2q+8..]
    uint32_t af[4][4];
    {
        const size_t r0 = (size_t)(b * RPB + w * 16 + g) * DIMK;
        const size_t r1 = r0 + 8 * DIMK;
        #pragma unroll
        for (int kt = 0; kt < 4; kt++) {
            const int k0 = kt * 16 + q * 2;
            float2 v00 = __ldg((const float2*)(z + r0 + k0));
            float2 v10 = __ldg((const float2*)(z + r1 + k0));
            float2 v01 = __ldg((const float2*)(z + r0 + k0 + 8));
            float2 v11 = __ldg((const float2*)(z + r1 + k0 + 8));
            af[kt][0] = bf2(v00.x, v00.y);
            af[kt][1] = bf2(v10.x, v10.y);
            af[kt][2] = bf2(v01.x, v01.y);
            af[kt][3] = bf2(v11.x, v11.y);
        }
    }

    // per-lane approx top-4 keys per owned row (rows: [h] = w*16 + g + h*8)
    int ck[2][4];
    #pragma unroll
    for (int h = 0; h < 2; h++)
        #pragma unroll
        for (int s = 0; s < 4; s++) ck[h][s] = 0x7FFFFFFF;

    const size_t encbase = OFF_ENC + (size_t)b * RPB * (TOPKK * CB);

    for (int c = 0; c < NCHUNK; c++) {
        if (c) __syncthreads();   // previous chunk's Bs reads complete
        // ---- stage B chunk: 128 codes, half-row per thread -> bf16 smem ----
        {
            const int code = t >> 1;
            const int half = t & 1;
            const float4* er = (const float4*)(emb + (size_t)(c * CHUNK + code) * DIMK + half * 32);
            uint32_t* dst = (uint32_t*)(Bs + code * BSTRIDE) + half * 16;
            #pragma unroll
            for (int i = 0; i < 8; i++) {
                float4 v = __ldg(er + i);
                dst[2 * i]     = bf2(v.x, v.y);
                dst[2 * i + 1] = bf2(v.z, v.w);
            }
        }
        // ---- overlap: zero 1/8 of this block's one-hot slice ----
        {
            const size_t cb = encbase + (size_t)c * 49152;   // ≡ 2 (mod 4)
            if (t == 0) {
                *(float2*)(out + cb) = make_float2(0.f, 0.f);
                *(float2*)(out + cb + 49150) = make_float2(0.f, 0.f);
            }
            float4* d4 = (float4*)(out + cb + 2);
            const float4 zz = make_float4(0.f, 0.f, 0.f, 0.f);
            for (int i = t; i < 12287; i += THREADS) d4[i] = zz;
        }
        __syncthreads();

        // ---- MMA over 16 n-tiles of 8 codes; 2 independent K-chains ----
        for (int nt = 0; nt < 16; nt++) {
            const int cb = nt * 8;
            // B frags: b0=[2q..][col g], b1=[2q+8..][col g]  (banks 4g+q: conflict-free)
            const uint16_t* bp = Bs + (cb + g) * BSTRIDE + q * 2;
            uint32_t bf[4][2];
            #pragma unroll
            for (int kt = 0; kt < 4; kt++) {
                bf[kt][0] = *(const uint32_t*)(bp + kt * 16);
                bf[kt][1] = *(const uint32_t*)(bp + kt * 16 + 8);
            }
            const float2 es22 = *(const float2*)&esq22_s[c * CHUNK + cb + q * 2];
            const int code0 = c * CHUNK + cb + q * 2;

            float x0 = 0.f, x1 = 0.f, x2 = 0.f, x3 = 0.f;   // chain A: kt 0,1
            float y0 = 0.f, y1 = 0.f, y2 = 0.f, y3 = 0.f;   // chain B: kt 2,3
            #pragma unroll
            for (int kt = 0; kt < 2; kt++) {
                asm volatile(
                    "mma.sync.aligned.m16n8k16.row.col.f32.bf16.bf16.f32 "
                    "{%0,%1,%2,%3}, {%4,%5,%6,%7}, {%8,%9}, {%0,%1,%2,%3};"
                    : "+f"(x0), "+f"(x1), "+f"(x2), "+f"(x3)
                    : "r"(af[kt][0]), "r"(af[kt][1]), "r"(af[kt][2]), "r"(af[kt][3]),
                      "r"(bf[kt][0]), "r"(bf[kt][1]));
                asm volatile(
                    "mma.sync.aligned.m16n8k16.row.col.f32.bf16.bf16.f32 "
                    "{%0,%1,%2,%3}, {%4,%5,%6,%7}, {%8,%9}, {%0,%1,%2,%3};"
                    : "+f"(y0), "+f"(y1), "+f"(y2), "+f"(y3)
                    : "r"(af[kt+2][0]), "r"(af[kt+2][1]), "r"(af[kt+2][2]), "r"(af[kt+2][3]),
                      "r"(bf[kt+2][0]), "r"(bf[kt+2][1]));
            }
            const float d0 = x0 + y0, d1 = x1 + y1, d2 = x2 + y2, d3 = x3 + y3;

            // key = round((esq - 2*dot) * 2^22) * 1024 + code  (monotone in d per row)
            // D map: d0,d1 = row g cols 2q,2q+1 ; d2,d3 = row g+8
            int k0 = __float2int_rn(fmaf(d0, -8388608.0f, es22.x));
            int k1 = __float2int_rn(fmaf(d1, -8388608.0f, es22.y));
            int k2 = __float2int_rn(fmaf(d2, -8388608.0f, es22.x));
            int k3 = __float2int_rn(fmaf(d3, -8388608.0f, es22.y));
            insk(k0 * 1024 + code0,     ck[0]);
            insk(k1 * 1024 + code0 + 1, ck[0]);
            insk(k2 * 1024 + code0,     ck[1]);
            insk(k3 * 1024 + code0 + 1, ck[1]);
        }
    }

    // ---- exact fp32 rescore of 4 candidates per owned row, then exact merge ----
    #pragma unroll
    for (int h = 0; h < 2; h++) {
        const int lr   = w * 16 + g + h * 8;
        const float zq = zsq_s[lr];
        const float4* z4 = (const float4*)(z + (size_t)(b * RPB + lr) * DIMK);
        float fs0 = 3.4e38f, fs1 = 3.4e38f, fs2 = 3.4e38f;
        int   fi0 = 0, fi1 = 0, fi2 = 0;
        #pragma unroll
        for (int s = 0; s < 4; s++) {
            const int gi = (int)((unsigned)ck[h][s] & 1023u);
            const float4* e4 = (const float4*)(emb + (size_t)gi * DIMK);
            float a0 = 0.f, a1 = 0.f, a2 = 0.f, a3 = 0.f;
            #pragma unroll
            for (int i = 0; i < 16; i++) {
                float4 ev = __ldg(e4 + i);
                float4 zv = __ldg(z4 + i);
                a0 = fmaf(zv.x, ev.x, a0);
                a1 = fmaf(zv.y, ev.y, a1);
                a2 = fmaf(zv.z, ev.z, a2);
                a3 = fmaf(zv.w, ev.w, a3);
            }
            float dot = __fadd_rn(__fadd_rn(a0, a1), __fadd_rn(a2, a3));
            float d   = __fsub_rn(__fadd_rn(zq, esq_s[gi]), __fmul_rn(2.0f, dot));
            ins3(d, gi, fs0, fs1, fs2, fi0, fi1, fi2);
        }
        // merge exact top-3 across the 4 lanes of this quad (disjoint code sets)
        #pragma unroll
        for (int off = 1; off <= 2; off <<= 1) {
            float e0 = __shfl_xor_sync(0xffffffffu, fs0, off);
            float e1 = __shfl_xor_sync(0xffffffffu, fs1, off);
            float e2 = __shfl_xor_sync(0xffffffffu, fs2, off);
            int   j0 = __shfl_xor_sync(0xffffffffu, fi0, off);
            int   j1 = __shfl_xor_sync(0xffffffffu, fi1, off);
            int   j2 = __shfl_xor_sync(0xffffffffu, fi2, off);
            ins3(e0, j0, fs0, fs1, fs2, fi0, fi1, fi2);
            ins3(e1, j1, fs0, fs1, fs2, fi0, fi1, fi2);
            ins3(e2, j2, fs0, fs1, fs2, fi0, fi1, fi2);
        }
        if (q == 0) {
            tidx[lr * 3 + 0] = fi0;
            tidx[lr * 3 + 1] = fi1;
            tidx[lr * 3 + 2] = fi2;
        }
    }
    __syncthreads();

    // ---- epilogue: thread t < 128 owns local row t ----
    if (t < RPB) {
        const int row = b * RPB + t;
        const int a0 = tidx[t * 3 + 0], a1 = tidx[t * 3 + 1], a2 = tidx[t * 3 + 2];
        const float4* e0 = (const float4*)(emb + (size_t)a0 * DIMK);
        const float4* e1 = (const float4*)(emb + (size_t)a1 * DIMK);
        const float4* e2 = (const float4*)(emb + (size_t)a2 * DIMK);
        const float4* z4 = (const float4*)(z + (size_t)row * DIMK);
        float4* zqout = (float4*)(out + (size_t)row * DIMK);
        float ls = 0.f;
        #pragma unroll
        for (int i = 0; i < 16; i++) {
            float4 v0 = __ldg(e0 + i), v1 = __ldg(e1 + i), v2 = __ldg(e2 + i);
            float4 zv = __ldg(z4 + i);
            float4 qv;
            qv.x = __fdiv_rn(__fadd_rn(__fadd_rn(v0.x, v1.x), v2.x), 3.0f);
            qv.y = __fdiv_rn(__fadd_rn(__fadd_rn(v0.y, v1.y), v2.y), 3.0f);
            qv.z = __fdiv_rn(__fadd_rn(__fadd_rn(v0.z, v1.z), v2.z), 3.0f);
            qv.w = __fdiv_rn(__fadd_rn(__fadd_rn(v0.w, v1.w), v2.w), 3.0f);
            float dx = qv.x - zv.x; ls += dx*dx;
            dx = qv.y - zv.y; ls += dx*dx;
            dx = qv.z - zv.z; ls += dx*dx;
            dx = qv.w - zv.w; ls += dx*dx;
            zqout[i] = qv;   // straight-through: z_q_st == z_q numerically
        }
        int idxs[3] = { a0, a1, a2 };
        #pragma unroll
        for (int s = 0; s < TOPKK; s++) {
            out[OFF_IDX + (size_t)row * TOPKK + s] = (float)idxs[s];
            out[OFF_ENC + (size_t)row * (TOPKK * CB) + (size_t)s * CB + idxs[s]] = 1.0f;
            atomicAdd(&g_hist[idxs[s]], 1u);
        }
        #pragma unroll
        for (int off = 16; off > 0; off >>= 1)
            ls += __shfl_xor_sync(0xffffffffu, ls, off);
        if (lane == 0) red[w] = ls;   // w in 0..3 for t<128
    }
    __syncthreads();
    if (t == 0) {
        g_blk_loss[b] = red[0] + red[1] + red[2] + red[3];
        __threadfence();
        unsigned int k = atomicAdd(&g_done, 1u);
        lastf = (k == NBLOCKS - 1) ? 1 : 0;
    }
    __syncthreads();

    // ---- finisher: loss & perplexity; self-clean state for graph replay ----
    if (lastf) {
        __threadfence();
        float term = 0.f;
        #pragma unroll
        for (int i = 0; i < 4; i++) {
            unsigned int h = g_hist[t * 4 + i];
            float pp = (float)h * (1.0f / 196608.0f);
            term += pp * logf(pp + 1e-10f);
            g_hist[t * 4 + i] = 0u;
        }
        float lsum = g_blk_loss[t] + g_blk_loss[t + 256];
        #pragma unroll
        for (int off = 16; off > 0; off >>= 1) {
            term += __shfl_xor_sync(0xffffffffu, term, off);
            lsum += __shfl_xor_sync(0xffffffffu, lsum, off);
        }
        if (lane == 0) { red[w] = term; red[8 + w] = lsum; }
        __syncthreads();
        if (t == 0) {
            float tt = 0.f, ll = 0.f;
            #pragma unroll
            for (int i = 0; i < 8; i++) { tt += red[i]; ll += red[8 + i]; }
            float m = ll * (1.0f / 4194304.0f);
            out[OFF_LOSS] = __fadd_rn(__fmul_rn(0.25f, m), m);   // beta*m + m
            out[OFF_PERP] = expf(-tt);
            g_done = 0u;
        }
    }
}

extern "C" void kernel_launch(void* const* d_in, const int* in_sizes, int n_in,
                              void* d_out, int out_size) {
    const float* z   = (const float*)d_in[0];
    const float* emb = (const float*)d_in[1];
    float* out = (float*)d_out;
    (void)in_sizes; (void)n_in; (void)out_size;
    vq_mma<<<NBLOCKS, THREADS>>>(z, emb, out);
}

// round 17
// speedup vs baseline: 1.1697x; 1.1697x over previous
#include <cuda_runtime.h>
#include <cuda_bf16.h>
#include <math.h>
#include <stdint.h>

#define NROWS    65536
#define DIMK     64
#define CB       1024
#define TOPKK    3
#define THREADS  256
#define NBLOCKS  512
#define RPB      128
#define CHUNK    128
#define NCHUNK   8
#define BSTRIDE  72       // bf16 per code row in smem: bank-spread stride

// Output layout (concatenated reference tuple, fp32):
//   z_q_st [4194304] | loss [1] | perplexity [1] | encodings [201326592] | idx [196608]
#define OFF_LOSS 4194304ull
#define OFF_PERP 4194305ull
#define OFF_ENC  4194306ull   // float index % 4 == 2 -> 8B-aligned base
#define OFF_IDX  205520898ull

__device__ unsigned int g_hist[CB];
__device__ float        g_blk_loss[NBLOCKS];
__device__ unsigned int g_done;

static __device__ __forceinline__ uint32_t bf2(float lo, float hi) {
    uint32_t r;
    asm("cvt.rn.bf16x2.f32 %0, %1, %2;" : "=r"(r) : "f"(hi), "f"(lo));
    return r;
}

// branchless insert of key v into ascending sorted 4-array (IMNMX chain)
static __device__ __forceinline__ void insk(int v, int* ck) {
    #pragma unroll
    for (int s = 0; s < 4; s++) {
        int mn = min(ck[s], v);
        int mx = max(ck[s], v);
        ck[s] = mn; v = mx;
    }
}
// insert (d, gi) into sorted triple, lexicographic (tie -> lower idx)
static __device__ __forceinline__ void ins3(float d, int gi,
                                            float& s0, float& s1, float& s2,
                                            int& i0, int& i1, int& i2) {
    if (d < s2 || (d == s2 && gi < i2)) {
        if (d < s1 || (d == s1 && gi < i1)) {
            s2 = s1; i2 = i1;
            if (d < s0 || (d == s0 && gi < i0)) { s1 = s0; i1 = i0; s0 = d; i0 = gi; }
            else                                { s1 = d;  i1 = gi; }
        } else { s2 = d; i2 = gi; }
    }
}

__global__ void __launch_bounds__(THREADS, 3) vq_mma(
    const float* __restrict__ z, const float* __restrict__ emb, float* __restrict__ out)
{
    __shared__ __align__(16) uint16_t Bs[CHUNK * BSTRIDE];   // bf16 codebook chunk
    __shared__ float esq_s[CB];     // |e|^2 exact (rescore)
    __shared__ float esq22_s[CB];   // |e|^2 * 2^22 (key path)
    __shared__ float zsq_s[RPB];
    __shared__ int   tidx[RPB * 3];
    __shared__ float red[16];
    __shared__ int   lastf;

    const int t    = threadIdx.x;
    const int b    = blockIdx.x;
    const int lane = t & 31;
    const int w    = t >> 5;          // warp 0..7: owns rows w*16 .. w*16+15
    const int g    = lane >> 2;       // group 0..7 (row-in-tile / B column)
    const int q    = lane & 3;        // quad 0..3  (k-pair / D column pair)

    // ---- |z|^2 for rows (first 128 threads) ----
    if (t < RPB) {
        const float4* zr = (const float4*)(z + (size_t)(b * RPB + t) * DIMK);
        float s = 0.f;
        #pragma unroll
        for (int i = 0; i < 16; i++) {
            float4 v = __ldg(zr + i);
            s += v.x*v.x; s += v.y*v.y; s += v.z*v.z; s += v.w*v.w;
        }
        zsq_s[t] = s;
    }
    // ---- |e|^2 for all 1024 codes (exact + scaled key base) ----
    #pragma unroll
    for (int p = 0; p < 4; p++) {
        const int code = p * THREADS + t;
        const float4* er = (const float4*)(emb + (size_t)code * DIMK);
        float s = 0.f;
        #pragma unroll
        for (int i = 0; i < 16; i++) {
            float4 v = __ldg(er + i);
            s += v.x*v.x; s += v.y*v.y; s += v.z*v.z; s += v.w*v.w;
        }
        esq_s[code]   = s;
        esq22_s[code] = s * 4194304.0f;   // 2^22
    }
    __syncthreads();

    // ---- A fragments: this warp's 16 z rows as bf16, register-resident ----
    // m16n8k16 A map: a0=[g][2q,2q+1] a1=[g+8][..] a2=[g][2q+8..] a3=[g+8][2q+8..]
    uint32_t af[4][4];
    {
        const size_t r0 = (size_t)(b * RPB + w * 16 + g) * DIMK;
        const size_t r1 = r0 + 8 * DIMK;
        #pragma unroll
        for (int kt = 0; kt < 4; kt++) {
            const int k0 = kt * 16 + q * 2;
            float2 v00 = __ldg((const float2*)(z + r0 + k0));
            float2 v10 = __ldg((const float2*)(z + r1 + k0));
            float2 v01 = __ldg((const float2*)(z + r0 + k0 + 8));
            float2 v11 = __ldg((const float2*)(z + r1 + k0 + 8));
            af[kt][0] = bf2(v00.x, v00.y);
            af[kt][1] = bf2(v10.x, v10.y);
            af[kt][2] = bf2(v01.x, v01.y);
            af[kt][3] = bf2(v11.x, v11.y);
        }
    }

    // per-lane approx top-4 keys per owned row (rows: [h] = w*16 + g + h*8)
    int ck[2][4];
    #pragma unroll
    for (int h = 0; h < 2; h++)
        #pragma unroll
        for (int s = 0; s < 4; s++) ck[h][s] = 0x7FFFFFFF;

    const size_t encbase = OFF_ENC + (size_t)b * RPB * (TOPKK * CB);

    for (int c = 0; c < NCHUNK; c++) {
        if (c) __syncthreads();   // previous chunk's Bs reads complete
        // ---- stage B chunk: 128 codes, half-row per thread -> bf16 smem ----
        {
            const int code = t >> 1;
            const int half = t & 1;
            const float4* er = (const float4*)(emb + (size_t)(c * CHUNK + code) * DIMK + half * 32);
            uint32_t* dst = (uint32_t*)(Bs + code * BSTRIDE) + half * 16;
            #pragma unroll
            for (int i = 0; i < 8; i++) {
                float4 v = __ldg(er + i);
                dst[2 * i]     = bf2(v.x, v.y);
                dst[2 * i + 1] = bf2(v.z, v.w);
            }
        }
        // ---- overlap: zero 1/8 of this block's one-hot slice ----
        {
            const size_t cb = encbase + (size_t)c * 49152;   // ≡ 2 (mod 4)
            if (t == 0) {
                *(float2*)(out + cb) = make_float2(0.f, 0.f);
                *(float2*)(out + cb + 49150) = make_float2(0.f, 0.f);
            }
            float4* d4 = (float4*)(out + cb + 2);
            const float4 zz = make_float4(0.f, 0.f, 0.f, 0.f);
            for (int i = t; i < 12287; i += THREADS) d4[i] = zz;
        }
        __syncthreads();

        // ---- MMA over 16 n-tiles of 8 codes; 2 independent K-chains ----
        for (int nt = 0; nt < 16; nt++) {
            const int cb = nt * 8;
            // B frags: b0=[2q..][col g], b1=[2q+8..][col g]  (banks 4g+q: conflict-free)
            const uint16_t* bp = Bs + (cb + g) * BSTRIDE + q * 2;
            uint32_t bf[4][2];
            #pragma unroll
            for (int kt = 0; kt < 4; kt++) {
                bf[kt][0] = *(const uint32_t*)(bp + kt * 16);
                bf[kt][1] = *(const uint32_t*)(bp + kt * 16 + 8);
            }
            const float2 es22 = *(const float2*)&esq22_s[c * CHUNK + cb + q * 2];
            const int code0 = c * CHUNK + cb + q * 2;

            float x0 = 0.f, x1 = 0.f, x2 = 0.f, x3 = 0.f;   // chain A: kt 0,1
            float y0 = 0.f, y1 = 0.f, y2 = 0.f, y3 = 0.f;   // chain B: kt 2,3
            #pragma unroll
            for (int kt = 0; kt < 2; kt++) {
                asm volatile(
                    "mma.sync.aligned.m16n8k16.row.col.f32.bf16.bf16.f32 "
                    "{%0,%1,%2,%3}, {%4,%5,%6,%7}, {%8,%9}, {%0,%1,%2,%3};"
                    : "+f"(x0), "+f"(x1), "+f"(x2), "+f"(x3)
                    : "r"(af[kt][0]), "r"(af[kt][1]), "r"(af[kt][2]), "r"(af[kt][3]),
                      "r"(bf[kt][0]), "r"(bf[kt][1]));
                asm volatile(
                    "mma.sync.aligned.m16n8k16.row.col.f32.bf16.bf16.f32 "
                    "{%0,%1,%2,%3}, {%4,%5,%6,%7}, {%8,%9}, {%0,%1,%2,%3};"
                    : "+f"(y0), "+f"(y1), "+f"(y2), "+f"(y3)
                    : "r"(af[kt+2][0]), "r"(af[kt+2][1]), "r"(af[kt+2][2]), "r"(af[kt+2][3]),
                      "r"(bf[kt+2][0]), "r"(bf[kt+2][1]));
            }
            const float d0 = x0 + y0, d1 = x1 + y1, d2 = x2 + y2, d3 = x3 + y3;

            // key = round((esq - 2*dot) * 2^22) * 1024 + code  (monotone in d per row)
            // D map: d0,d1 = row g cols 2q,2q+1 ; d2,d3 = row g+8
            int k0 = __float2int_rn(fmaf(d0, -8388608.0f, es22.x));
            int k1 = __float2int_rn(fmaf(d1, -8388608.0f, es22.y));
            int k2 = __float2int_rn(fmaf(d2, -8388608.0f, es22.x));
            int k3 = __float2int_rn(fmaf(d3, -8388608.0f, es22.y));
            insk(k0 * 1024 + code0,     ck[0]);
            insk(k1 * 1024 + code0 + 1, ck[0]);
            insk(k2 * 1024 + code0,     ck[1]);
            insk(k3 * 1024 + code0 + 1, ck[1]);
        }
    }

    // ---- quad-cooperative exact fp32 rescore ----
    // The 4 lanes of a quad own the SAME two rows with 4 disjoint candidates
    // each. Broadcast each of the 16 candidates; each lane computes a 16-dim
    // partial dot (dims [16q,16q+16)); butterfly-sum within the quad. All 4
    // lanes then hold identical exact distances -> identical top-3; no merge.
    #pragma unroll
    for (int h = 0; h < 2; h++) {
        const int lr   = w * 16 + g + h * 8;
        const float zq = zsq_s[lr];
        const float4* z4 = (const float4*)(z + (size_t)(b * RPB + lr) * DIMK);
        float4 zp[4];
        #pragma unroll
        for (int i = 0; i < 4; i++) zp[i] = __ldg(z4 + q * 4 + i);

        float fs0 = 3.4e38f, fs1 = 3.4e38f, fs2 = 3.4e38f;
        int   fi0 = 0, fi1 = 0, fi2 = 0;
        #pragma unroll
        for (int s = 0; s < 4; s++) {
            #pragma unroll
            for (int qs = 0; qs < 4; qs++) {
                const int key = __shfl_sync(0xffffffffu, ck[h][s], (lane & ~3) | qs);
                const int gi  = (int)((unsigned)key & 1023u);
                const float4* e4 = (const float4*)(emb + (size_t)gi * DIMK) + q * 4;
                float a0 = 0.f, a1 = 0.f, a2 = 0.f, a3 = 0.f;
                #pragma unroll
                for (int i = 0; i < 4; i++) {
                    float4 ev = __ldg(e4 + i);
                    a0 = fmaf(zp[i].x, ev.x, a0);
                    a1 = fmaf(zp[i].y, ev.y, a1);
                    a2 = fmaf(zp[i].z, ev.z, a2);
                    a3 = fmaf(zp[i].w, ev.w, a3);
                }
                float part = __fadd_rn(__fadd_rn(a0, a1), __fadd_rn(a2, a3));
                part += __shfl_xor_sync(0xffffffffu, part, 1);
                part += __shfl_xor_sync(0xffffffffu, part, 2);
                const float d = __fsub_rn(__fadd_rn(zq, esq_s[gi]), __fmul_rn(2.0f, part));
                ins3(d, gi, fs0, fs1, fs2, fi0, fi1, fi2);
            }
        }
        if (q == 0) {
            tidx[lr * 3 + 0] = fi0;
            tidx[lr * 3 + 1] = fi1;
            tidx[lr * 3 + 2] = fi2;
        }
    }
    __syncthreads();

    // ---- epilogue: thread t < 128 owns local row t ----
    if (t < RPB) {
        const int row = b * RPB + t;
        const int a0 = tidx[t * 3 + 0], a1 = tidx[t * 3 + 1], a2 = tidx[t * 3 + 2];
        const float4* e0 = (const float4*)(emb + (size_t)a0 * DIMK);
        const float4* e1 = (const float4*)(emb + (size_t)a1 * DIMK);
        const float4* e2 = (const float4*)(emb + (size_t)a2 * DIMK);
        const float4* z4 = (const float4*)(z + (size_t)row * DIMK);
        float4* zqout = (float4*)(out + (size_t)row * DIMK);
        float ls = 0.f;
        #pragma unroll
        for (int i = 0; i < 16; i++) {
            float4 v0 = __ldg(e0 + i), v1 = __ldg(e1 + i), v2 = __ldg(e2 + i);
            float4 zv = __ldg(z4 + i);
            float4 qv;
            qv.x = __fdiv_rn(__fadd_rn(__fadd_rn(v0.x, v1.x), v2.x), 3.0f);
            qv.y = __fdiv_rn(__fadd_rn(__fadd_rn(v0.y, v1.y), v2.y), 3.0f);
            qv.z = __fdiv_rn(__fadd_rn(__fadd_rn(v0.z, v1.z), v2.z), 3.0f);
            qv.w = __fdiv_rn(__fadd_rn(__fadd_rn(v0.w, v1.w), v2.w), 3.0f);
            float dx = qv.x - zv.x; ls += dx*dx;
            dx = qv.y - zv.y; ls += dx*dx;
            dx = qv.z - zv.z; ls += dx*dx;
            dx = qv.w - zv.w; ls += dx*dx;
            zqout[i] = qv;   // straight-through: z_q_st == z_q numerically
        }
        int idxs[3] = { a0, a1, a2 };
        #pragma unroll
        for (int s = 0; s < TOPKK; s++) {
            out[OFF_IDX + (size_t)row * TOPKK + s] = (float)idxs[s];
            out[OFF_ENC + (size_t)row * (TOPKK * CB) + (size_t)s * CB + idxs[s]] = 1.0f;
            atomicAdd(&g_hist[idxs[s]], 1u);
        }
        #pragma unroll
        for (int off = 16; off > 0; off >>= 1)
            ls += __shfl_xor_sync(0xffffffffu, ls, off);
        if (lane == 0) red[w] = ls;   // w in 0..3 for t<128
    }
    __syncthreads();
    if (t == 0) {
        g_blk_loss[b] = red[0] + red[1] + red[2] + red[3];
        __threadfence();
        unsigned int k = atomicAdd(&g_done, 1u);
        lastf = (k == NBLOCKS - 1) ? 1 : 0;
    }
    __syncthreads();

    // ---- finisher: loss & perplexity; self-clean state for graph replay ----
    if (lastf) {
        __threadfence();
        float term = 0.f;
        #pragma unroll
        for (int i = 0; i < 4; i++) {
            unsigned int h = g_hist[t * 4 + i];
            float pp = (float)h * (1.0f / 196608.0f);
            term += pp * logf(pp + 1e-10f);
            g_hist[t * 4 + i] = 0u;
        }
        float lsum = g_blk_loss[t] + g_blk_loss[t + 256];
        #pragma unroll
        for (int off = 16; off > 0; off >>= 1) {
            term += __shfl_xor_sync(0xffffffffu, term, off);
            lsum += __shfl_xor_sync(0xffffffffu, lsum, off);
        }
        if (lane == 0) { red[w] = term; red[8 + w] = lsum; }
        __syncthreads();
        if (t == 0) {
            float tt = 0.f, ll = 0.f;
            #pragma unroll
            for (int i = 0; i < 8; i++) { tt += red[i]; ll += red[8 + i]; }
            float m = ll * (1.0f / 4194304.0f);
            out[OFF_LOSS] = __fadd_rn(__fmul_rn(0.25f, m), m);   // beta*m + m
            out[OFF_PERP] = expf(-tt);
            g_done = 0u;
        }
    }
}

extern "C" void kernel_launch(void* const* d_in, const int* in_sizes, int n_in,
                              void* d_out, int out_size) {
    const float* z   = (const float*)d_in[0];
    const float* emb = (const float*)d_in[1];
    float* out = (float*)d_out;
    (void)in_sizes; (void)n_in; (void)out_size;
    vq_mma<<<NBLOCKS, THREADS>>>(z, emb, out);
}